// round 1
// baseline (speedup 1.0000x reference)
#include <cuda_runtime.h>

// CensusLoss: 5x5 census transform hamming distance, reflect padding, mean.
// Shapes fixed by the problem: pred/gt = (8, 3, 512, 512) fp32.

#define HH   512
#define WW   512
#define NIMG 24            // B*C = 8*3
#define TW   128           // output tile width per block
#define TH   8             // output tile height per block
#define SW   (TW + 4)      // 132 (halo of 2 each side)
#define SH   (TH + 4)      // 12
#define NELEM 6291456.0    // 8*3*512*512

__device__ unsigned int g_acc;

__global__ void zero_acc_kernel() { g_acc = 0u; }

__global__ void finalize_kernel(float* out) {
    out[0] = (float)((double)g_acc / NELEM);
}

// jnp.pad mode='reflect' (edge not repeated): i<0 -> -i ; i>=n -> 2n-2-i
__device__ __forceinline__ int refl(int i, int n) {
    i = (i < 0) ? -i : i;
    return (i >= n) ? (2 * n - 2 - i) : i;
}

__global__ __launch_bounds__(256)
void census_kernel(const float* __restrict__ pred, const float* __restrict__ gt)
{
    __shared__ __align__(16) float sp[SH][SW];
    __shared__ __align__(16) float sg[SH][SW];
    __shared__ int warp_sums[8];

    const int img  = blockIdx.z;
    const int row0 = blockIdx.y * TH;
    const int col0 = blockIdx.x * TW;
    const float* __restrict__ p = pred + (size_t)img * HH * WW;
    const float* __restrict__ g = gt   + (size_t)img * HH * WW;

    const int tid = threadIdx.y * 32 + threadIdx.x;

    // Cooperative halo load with reflect indexing (1584 elems per tensor).
    for (int idx = tid; idx < SH * SW; idx += 256) {
        int lr = idx / SW;
        int lc = idx - lr * SW;
        int gr = refl(row0 + lr - 2, HH);
        int gc = refl(col0 + lc - 2, WW);
        sp[lr][lc] = p[gr * WW + gc];
        sg[lr][lc] = g[gr * WW + gc];
    }
    __syncthreads();

    const int ty = threadIdx.y;        // output row within tile
    const int bx = threadIdx.x * 4;    // local col base of 4-pixel micro-tile

    // Centers for the 4 output pixels (smem row ty+2, cols bx+2..bx+5)
    const float pc0 = sp[ty + 2][bx + 2];
    const float pc1 = sp[ty + 2][bx + 3];
    const float pc2 = sp[ty + 2][bx + 4];
    const float pc3 = sp[ty + 2][bx + 5];
    const float gc0 = sg[ty + 2][bx + 2];
    const float gc1 = sg[ty + 2][bx + 3];
    const float gc2 = sg[ty + 2][bx + 4];
    const float gc3 = sg[ty + 2][bx + 5];

    int acc = 0;
    #pragma unroll
    for (int dr = 0; dr < 5; ++dr) {
        const float4 pa = *reinterpret_cast<const float4*>(&sp[ty + dr][bx]);
        const float4 pb = *reinterpret_cast<const float4*>(&sp[ty + dr][bx + 4]);
        const float4 ga = *reinterpret_cast<const float4*>(&sg[ty + dr][bx]);
        const float4 gb = *reinterpret_cast<const float4*>(&sg[ty + dr][bx + 4]);
        const float pr[8] = {pa.x, pa.y, pa.z, pa.w, pb.x, pb.y, pb.z, pb.w};
        const float gr8[8] = {ga.x, ga.y, ga.z, ga.w, gb.x, gb.y, gb.z, gb.w};
        #pragma unroll
        for (int dc = 0; dc < 5; ++dc) {
            if (dr == 2 && dc == 2) continue;   // skip center-vs-center
            acc += (int)((pr[dc + 0] < pc0) ^ (gr8[dc + 0] < gc0));
            acc += (int)((pr[dc + 1] < pc1) ^ (gr8[dc + 1] < gc1));
            acc += (int)((pr[dc + 2] < pc2) ^ (gr8[dc + 2] < gc2));
            acc += (int)((pr[dc + 3] < pc3) ^ (gr8[dc + 3] < gc3));
        }
    }

    // Warp reduce (integer, exact, deterministic)
    #pragma unroll
    for (int o = 16; o; o >>= 1)
        acc += __shfl_xor_sync(0xffffffffu, acc, o);
    if (threadIdx.x == 0) warp_sums[threadIdx.y] = acc;
    __syncthreads();
    if (tid == 0) {
        int s = 0;
        #pragma unroll
        for (int w = 0; w < 8; ++w) s += warp_sums[w];
        atomicAdd(&g_acc, (unsigned int)s);   // one atomic per block
    }
}

extern "C" void kernel_launch(void* const* d_in, const int* in_sizes, int n_in,
                              void* d_out, int out_size)
{
    const float* pred = (const float*)d_in[0];
    const float* gt   = (const float*)d_in[1];
    float* out        = (float*)d_out;

    zero_acc_kernel<<<1, 1>>>();
    dim3 grid(WW / TW, HH / TH, NIMG);   // (4, 64, 24)
    dim3 block(32, 8);
    census_kernel<<<grid, block>>>(pred, gt);
    finalize_kernel<<<1, 1>>>(out);
}